// round 8
// baseline (speedup 1.0000x reference)
#include <cuda_runtime.h>
#include <math.h>

// ---------------------------------------------------------------------------
// Problem constants (fixed by dataset; runtime sizes still read from in_sizes)
// ---------------------------------------------------------------------------
#define D_C       128
#define PITCH     132          // z_sh row pitch (floats)
#define PITCHI    264          // paired-I row pitch (floats)
#define MAX_ITEMS 200000
#define MAX_USERS 100000
#define MAX_EII   3200000
#define MAX_EUI   1600000
#define MAX_EDGES (3 * MAX_EII + MAX_EUI)          // 11.2M
#define MAX_ROWS  (3 * MAX_ITEMS + MAX_USERS)      // 700K logical output rows
#define SCAN_CHUNK 4096
#define MAX_PARTS ((MAX_ROWS + SCAN_CHUNK - 1) / SCAN_CHUNK + 1)

// Static device scratch (no allocs allowed).
__device__ float g_nb  [(size_t)3 * MAX_ITEMS * D_C];   // 3 item->item aggregates
__device__ int2  g_bpk [MAX_EDGES];                     // binned (src, val-bits)
__device__ int   g_cnt [MAX_ROWS];                      // per-row edge counts
__device__ int   g_off [MAX_ROWS + 1];                  // CSR row offsets
__device__ int   g_cur [MAX_ROWS];                      // scatter cursors
__device__ int   g_part[MAX_PARTS];                     // scan block partials

// ---------------------------------------------------------------------------
// Pass 1: histogram of destination rows (4 edges / thread, int4 loads)
// ---------------------------------------------------------------------------
__global__ void hist_kernel(const int* __restrict__ dst, int nE, int base,
                            int* __restrict__ cnt)
{
    int i0 = (blockIdx.x * blockDim.x + threadIdx.x) * 4;
    if (i0 + 3 < nE) {
        int4 d = *reinterpret_cast<const int4*>(dst + i0);
        atomicAdd(&cnt[base + d.x], 1);
        atomicAdd(&cnt[base + d.y], 1);
        atomicAdd(&cnt[base + d.z], 1);
        atomicAdd(&cnt[base + d.w], 1);
    } else {
        for (int j = i0; j < nE; j++) atomicAdd(&cnt[base + dst[j]], 1);
    }
}

// ---------------------------------------------------------------------------
// Pass 2a: per-block sums (4096 elements / block)
// ---------------------------------------------------------------------------
__global__ void __launch_bounds__(1024)
block_sum_kernel(const int* __restrict__ cnt, int* __restrict__ part, int N)
{
    __shared__ int ws[32];
    const int tid = threadIdx.x, lane = tid & 31, wid = tid >> 5;
    int idx = blockIdx.x * SCAN_CHUNK + tid * 4;
    int t = 0;
    if (idx + 3 < N) {
        int4 v = *reinterpret_cast<const int4*>(cnt + idx);
        t = v.x + v.y + v.z + v.w;
    } else {
        for (int j = idx; j < min(idx + 4, N); j++) t += cnt[j];
    }
#pragma unroll
    for (int o = 16; o > 0; o >>= 1) t += __shfl_xor_sync(0xffffffffu, t, o);
    if (lane == 0) ws[wid] = t;
    __syncthreads();
    if (wid == 0) {
        int u = ws[lane];
#pragma unroll
        for (int o = 16; o > 0; o >>= 1) u += __shfl_xor_sync(0xffffffffu, u, o);
        if (lane == 0) part[blockIdx.x] = u;
    }
}

// ---------------------------------------------------------------------------
// Pass 2b: exclusive scan of the (<=1024) block partials; writes off[N]
// ---------------------------------------------------------------------------
__global__ void __launch_bounds__(1024)
part_scan_kernel(int* __restrict__ part, int nparts, int* __restrict__ off_total)
{
    __shared__ int wtot[32];
    const int tid = threadIdx.x, lane = tid & 31, wid = tid >> 5;
    int v = (tid < nparts) ? part[tid] : 0;
    int incl = v;
#pragma unroll
    for (int o = 1; o < 32; o <<= 1) {
        int u = __shfl_up_sync(0xffffffffu, incl, o);
        if (lane >= o) incl += u;
    }
    if (lane == 31) wtot[wid] = incl;
    __syncthreads();
    if (wid == 0) {
        int w = wtot[lane];
        int wi = w;
#pragma unroll
        for (int o = 1; o < 32; o <<= 1) {
            int u = __shfl_up_sync(0xffffffffu, wi, o);
            if (lane >= o) wi += u;
        }
        wtot[lane] = wi - w;     // exclusive warp offsets
    }
    __syncthreads();
    int excl = wtot[wid] + incl - v;
    if (tid < nparts) part[tid] = excl;
    if (tid == nparts - 1) *off_total = excl + v;   // off[N] = grand total
}

// ---------------------------------------------------------------------------
// Pass 2c: final scan — local 4096-chunk scan + per-block carry from part[]
// ---------------------------------------------------------------------------
__global__ void __launch_bounds__(1024)
scan_final_kernel(const int* __restrict__ cnt, const int* __restrict__ part,
                  int* __restrict__ off, int* __restrict__ cur, int N)
{
    __shared__ int wtot[32];
    __shared__ int wexcl[32];
    const int tid = threadIdx.x, lane = tid & 31, wid = tid >> 5;
    int idx = blockIdx.x * SCAN_CHUNK + tid * 4;

    int4 v = make_int4(0, 0, 0, 0);
    if (idx + 3 < N)      v = *reinterpret_cast<const int4*>(cnt + idx);
    else if (idx < N) {
        v.x = cnt[idx];
        if (idx + 1 < N) v.y = cnt[idx + 1];
        if (idx + 2 < N) v.z = cnt[idx + 2];
    }
    int t0 = v.x, t1 = t0 + v.y, t2 = t1 + v.z, t3 = t2 + v.w;

    int incl = t3;
#pragma unroll
    for (int o = 1; o < 32; o <<= 1) {
        int u = __shfl_up_sync(0xffffffffu, incl, o);
        if (lane >= o) incl += u;
    }
    int thr_excl = incl - t3;
    if (lane == 31) wtot[wid] = incl;
    __syncthreads();
    if (wid == 0) {
        int w = wtot[lane];
        int wi = w;
#pragma unroll
        for (int o = 1; o < 32; o <<= 1) {
            int u = __shfl_up_sync(0xffffffffu, wi, o);
            if (lane >= o) wi += u;
        }
        wexcl[lane] = wi - w;
    }
    __syncthreads();
    int ex = part[blockIdx.x] + wexcl[wid] + thr_excl;
    if (idx + 3 < N) {
        int4 o4 = make_int4(ex, ex + t0, ex + t1, ex + t2);
        *reinterpret_cast<int4*>(off + idx) = o4;
        *reinterpret_cast<int4*>(cur + idx) = o4;
    } else if (idx < N) {
        off[idx] = ex;           cur[idx] = ex;
        if (idx + 1 < N) { off[idx + 1] = ex + t0; cur[idx + 1] = ex + t0; }
        if (idx + 2 < N) { off[idx + 2] = ex + t1; cur[idx + 2] = ex + t1; }
    }
}

// ---------------------------------------------------------------------------
// Pass 3: scatter edges into destination bins — ONE packed 8B write per edge
// ---------------------------------------------------------------------------
__global__ void scatter_kernel(const int* __restrict__ src,
                               const int* __restrict__ dst,
                               const float* __restrict__ val,
                               int nE, int base, int* __restrict__ cur,
                               int2* __restrict__ bpk)
{
    int i = blockIdx.x * blockDim.x + threadIdx.x;
    if (i < nE) {
        int d   = dst[i];
        int pos = atomicAdd(&cur[base + d], 1);
        bpk[pos] = make_int2(src[i], __float_as_int(val[i]));
    }
}

// ---------------------------------------------------------------------------
// Pass 4: gather-accumulate. One warp per output row; 4-way unrolled edge
// groups give MLP=4 on the x gathers; single 512B store per row.
// ---------------------------------------------------------------------------
__global__ void __launch_bounds__(256)
gather_kernel(const int* __restrict__ off,
              const int2* __restrict__ bpk,
              const float* __restrict__ x,
              float* __restrict__ nb, float* __restrict__ uemb,
              int n3, int nrows)
{
    int w = (blockIdx.x * blockDim.x + threadIdx.x) >> 5;
    if (w >= nrows) return;
    const int lane = threadIdx.x & 31;

    unsigned long long pol;
    asm("createpolicy.fractional.L2::evict_last.b64 %0, 1.0;" : "=l"(pol));

    int beg = __ldg(off + w);
    int end = __ldg(off + w + 1);

    float4 a0 = make_float4(0.f, 0.f, 0.f, 0.f);
    float4 a1 = make_float4(0.f, 0.f, 0.f, 0.f);
    float4 a2 = make_float4(0.f, 0.f, 0.f, 0.f);
    float4 a3 = make_float4(0.f, 0.f, 0.f, 0.f);

#define XLOAD(T, SRC)                                                          \
    {                                                                          \
        const float* xp = x + (size_t)(SRC) * D_C + lane * 4;                  \
        asm volatile("ld.global.nc.L2::cache_hint.v4.f32 {%0,%1,%2,%3}, [%4], %5;" \
                     : "=f"(T.x), "=f"(T.y), "=f"(T.z), "=f"(T.w)              \
                     : "l"(xp), "l"(pol));                                     \
    }
#define XFMA(A, T, V)                                                          \
    A.x = fmaf(T.x, V, A.x); A.y = fmaf(T.y, V, A.y);                          \
    A.z = fmaf(T.z, V, A.z); A.w = fmaf(T.w, V, A.w);

    for (int p = beg; p < end; p += 32) {
        int n = min(32, end - p);
        int2 pk = make_int2(0, 0);
        if (lane < n) pk = __ldg(bpk + p + lane);

        int e = 0;
        for (; e + 4 <= n; e += 4) {
            int   s0 = __shfl_sync(0xffffffffu, pk.x, e);
            int   s1 = __shfl_sync(0xffffffffu, pk.x, e + 1);
            int   s2 = __shfl_sync(0xffffffffu, pk.x, e + 2);
            int   s3 = __shfl_sync(0xffffffffu, pk.x, e + 3);
            float v0 = __int_as_float(__shfl_sync(0xffffffffu, pk.y, e));
            float v1 = __int_as_float(__shfl_sync(0xffffffffu, pk.y, e + 1));
            float v2 = __int_as_float(__shfl_sync(0xffffffffu, pk.y, e + 2));
            float v3 = __int_as_float(__shfl_sync(0xffffffffu, pk.y, e + 3));
            float4 t0, t1, t2, t3;
            XLOAD(t0, s0); XLOAD(t1, s1); XLOAD(t2, s2); XLOAD(t3, s3);
            XFMA(a0, t0, v0); XFMA(a1, t1, v1); XFMA(a2, t2, v2); XFMA(a3, t3, v3);
        }
        for (; e < n; e++) {
            int   se = __shfl_sync(0xffffffffu, pk.x, e);
            float ve = __int_as_float(__shfl_sync(0xffffffffu, pk.y, e));
            float4 t; XLOAD(t, se); XFMA(a0, t, ve);
        }
    }
#undef XLOAD
#undef XFMA

    a0.x += a1.x + a2.x + a3.x;
    a0.y += a1.y + a2.y + a3.y;
    a0.z += a1.z + a2.z + a3.z;
    a0.w += a1.w + a2.w + a3.w;

    float* o = (w < n3) ? (nb + (size_t)w * D_C)
                        : (uemb + (size_t)(w - n3) * D_C);
    *reinterpret_cast<float4*>(o + lane * 4) = a0;
}

// ---------------------------------------------------------------------------
// Score + combine kernel: 64 rows / block, 512 threads, 2 blocks/SM.
// ---------------------------------------------------------------------------
__device__ __forceinline__ unsigned long long ld_u64_smem(const float* p)
{
    return *reinterpret_cast<const unsigned long long*>(p);
}

__global__ void __launch_bounds__(512, 2)
score_kernel(const float* __restrict__ x,
             const float* __restrict__ nb0,
             const float* __restrict__ nb1,
             const float* __restrict__ nb2,
             const float* __restrict__ I0,
             const float* __restrict__ I1,
             const float* __restrict__ I2,
             float* __restrict__ out,
             int nrows)
{
    extern __shared__ float sm[];
    float* I_sh = sm;                              // 64 * PITCHI (paired k rows)
    float* z_sh = sm + 64 * PITCHI;                // 64 * PITCH
    float* s_sh = sm + 64 * PITCHI + 64 * PITCH;   // 3 * 64

    const int tid  = threadIdx.x;
    const int lane = tid & 31;
    const int wid  = tid >> 5;                     // 16 warps
    const int r0   = wid << 2;                     // 4 rows per warp
    const int row0 = blockIdx.x * 64;
    const int rows = min(64, nrows - row0);

    const float4* xg = reinterpret_cast<const float4*>(x);

#pragma unroll 1
    for (int rel = 0; rel < 3; rel++) {
        const float* nbp = (rel == 0) ? nb0 : (rel == 1) ? nb1 : nb2;
        const float* Ip  = (rel == 0) ? I0  : (rel == 1) ? I1  : I2;

        const float4* Ig = reinterpret_cast<const float4*>(Ip);
        for (int idx = tid; idx < 64 * 32; idx += 512) {
            int p  = idx >> 5;
            int j4 = idx & 31;
            float4 ae = Ig[(2 * p)     * 32 + j4];
            float4 ao = Ig[(2 * p + 1) * 32 + j4];
            float* wp = &I_sh[p * PITCHI + (j4 << 3)];
            *reinterpret_cast<float4*>(wp)     = make_float4(ae.x, ao.x, ae.y, ao.y);
            *reinterpret_cast<float4*>(wp + 4) = make_float4(ae.z, ao.z, ae.w, ao.w);
        }
        const float4* ng = reinterpret_cast<const float4*>(nbp);
        for (int idx = tid; idx < 64 * 32; idx += 512) {
            int r  = idx >> 5;
            int k4 = idx & 31;
            float4 zv = make_float4(0.f, 0.f, 0.f, 0.f);
            if (r < rows) {
                size_t offr = (size_t)(row0 + r) * 32 + k4;
                float4 av = xg[offr];
                float4 bv = ng[offr];
                zv.x = av.x * bv.x; zv.y = av.y * bv.y;
                zv.z = av.z * bv.z; zv.w = av.w * bv.w;
            }
            *reinterpret_cast<float4*>(&z_sh[r * PITCH + (k4 << 2)]) = zv;
        }
        __syncthreads();

        unsigned long long acc[4][4];
#pragma unroll
        for (int r = 0; r < 4; r++)
#pragma unroll
            for (int c = 0; c < 4; c++) acc[r][c] = 0ull;

        for (int p = 0; p < 64; p++) {
            unsigned long long zp[4];
#pragma unroll
            for (int r = 0; r < 4; r++)
                zp[r] = ld_u64_smem(&z_sh[(r0 + r) * PITCH + 2 * p]);
#pragma unroll
            for (int c = 0; c < 4; c++) {
                unsigned long long bp =
                    ld_u64_smem(&I_sh[p * PITCHI + ((lane + 32 * c) << 1)]);
#pragma unroll
                for (int r = 0; r < 4; r++)
                    asm("fma.rn.f32x2 %0, %1, %2, %0;"
                        : "+l"(acc[r][c]) : "l"(zp[r]), "l"(bp));
            }
        }

#pragma unroll
        for (int r = 0; r < 4; r++) {
            float rs = 0.f;
#pragma unroll
            for (int c = 0; c < 4; c++) {
                float lo = __int_as_float((int)(acc[r][c] & 0xffffffffull));
                float hi = __int_as_float((int)(acc[r][c] >> 32));
                float h  = lo + hi;
                rs += (h >= 0.f) ? h : 0.2f * h;
            }
#pragma unroll
            for (int o = 16; o > 0; o >>= 1)
                rs += __shfl_xor_sync(0xffffffffu, rs, o);
            if (lane == 0)
                s_sh[rel * 64 + r0 + r] = rs * 0.08838834764831845f; // 1/sqrt(128)
        }
        __syncthreads();
    }

    const float4* n0g = reinterpret_cast<const float4*>(nb0);
    const float4* n1g = reinterpret_cast<const float4*>(nb1);
    const float4* n2g = reinterpret_cast<const float4*>(nb2);
    float4* og = reinterpret_cast<float4*>(out);

    for (int idx = tid; idx < 64 * 32; idx += 512) {
        int r  = idx >> 5;
        int c4 = idx & 31;
        if (r >= rows) continue;
        float s0 = s_sh[r];
        float s1 = s_sh[64 + r];
        float s2 = s_sh[128 + r];
        float m  = fmaxf(s0, fmaxf(s1, s2));
        float e0 = __expf(s0 - m);
        float e1 = __expf(s1 - m);
        float e2 = __expf(s2 - m);
        float inv = 1.f / (e0 + e1 + e2);
        float w0 = e0 * inv, w1 = e1 * inv, w2 = e2 * inv;

        size_t offr = (size_t)(row0 + r) * 32 + c4;
        float4 av = n0g[offr], bv = n1g[offr], cv = n2g[offr];
        float4 o;
        o.x = w0 * av.x + w1 * bv.x + w2 * cv.x;
        o.y = w0 * av.y + w1 * bv.y + w2 * cv.y;
        o.z = w0 * av.z + w1 * bv.z + w2 * cv.z;
        o.w = w0 * av.w + w1 * bv.w + w2 * cv.w;
        og[offr] = o;
    }
}

// ---------------------------------------------------------------------------
// Launch
// ---------------------------------------------------------------------------
extern "C" void kernel_launch(void* const* d_in, const int* in_sizes, int n_in,
                              void* d_out, int out_size)
{
    int base = (in_sizes[0] == 1) ? 1 : 0;

    const float* x      = (const float*)d_in[base + 0];
    const int*   srcs[4] = { (const int*)d_in[base + 1], (const int*)d_in[base + 4],
                             (const int*)d_in[base + 7], (const int*)d_in[base + 10] };
    const int*   dsts[4] = { (const int*)d_in[base + 2], (const int*)d_in[base + 5],
                             (const int*)d_in[base + 8], (const int*)d_in[base + 11] };
    const float* vals[4] = { (const float*)d_in[base + 3], (const float*)d_in[base + 6],
                             (const float*)d_in[base + 9], (const float*)d_in[base + 12] };
    const float* I0     = (const float*)d_in[base + 13];
    const float* I1     = (const float*)d_in[base + 14];
    const float* I2     = (const float*)d_in[base + 15];

    int n_items = in_sizes[base + 0] / D_C;
    int nE[4]   = { in_sizes[base + 1], in_sizes[base + 4],
                    in_sizes[base + 7], in_sizes[base + 10] };
    int n_users = out_size / D_C - n_items;
    int n3      = 3 * n_items;
    int nrows   = n3 + n_users;

    float* out_f    = (float*)d_out;
    float* u_emb    = out_f;                          // tuple order: (u_emb, neighbor)
    float* neighbor = out_f + (size_t)n_users * D_C;

    float *nb_base; int2 *bpk; int *cnt, *off, *cur, *part;
    cudaGetSymbolAddress((void**)&nb_base, g_nb);
    cudaGetSymbolAddress((void**)&bpk,     g_bpk);
    cudaGetSymbolAddress((void**)&cnt,     g_cnt);
    cudaGetSymbolAddress((void**)&off,     g_off);
    cudaGetSymbolAddress((void**)&cur,     g_cur);
    cudaGetSymbolAddress((void**)&part,    g_part);

    float* nb0 = nb_base;
    float* nb1 = nb_base + (size_t)n_items * D_C;
    float* nb2 = nb_base + (size_t)2 * n_items * D_C;

    // --- build CSR bins -----------------------------------------------------
    cudaMemsetAsync(cnt, 0, (size_t)nrows * sizeof(int), 0);
    for (int r = 0; r < 4; r++) {
        int b = (r < 3) ? r * n_items : n3;
        int g = ((nE[r] + 3) / 4 + 255) / 256;
        hist_kernel<<<g, 256>>>(dsts[r], nE[r], b, cnt);
    }
    int nparts = (nrows + SCAN_CHUNK - 1) / SCAN_CHUNK;
    block_sum_kernel<<<nparts, 1024>>>(cnt, part, nrows);
    part_scan_kernel<<<1, 1024>>>(part, nparts, off + nrows);
    scan_final_kernel<<<nparts, 1024>>>(cnt, part, off, cur, nrows);
    for (int r = 0; r < 4; r++) {
        int b = (r < 3) ? r * n_items : n3;
        int g = (nE[r] + 255) / 256;
        scatter_kernel<<<g, 256>>>(srcs[r], dsts[r], vals[r], nE[r], b, cur, bpk);
    }

    // --- gather-accumulate: writes nb0..2 and u_emb (no memset needed) -------
    {
        int g = ((nrows * 32) + 255) / 256;
        gather_kernel<<<g, 256>>>(off, bpk, x, nb_base, u_emb, n3, nrows);
    }

    // --- score + combine ------------------------------------------------------
    const int smem_bytes = (64 * PITCHI + 64 * PITCH + 3 * 64) * (int)sizeof(float);
    cudaFuncSetAttribute(score_kernel,
                         cudaFuncAttributeMaxDynamicSharedMemorySize, smem_bytes);
    int nblocks = (n_items + 63) / 64;
    score_kernel<<<nblocks, 512, smem_bytes>>>(x, nb0, nb1, nb2, I0, I1, I2,
                                               neighbor, n_items);
}

// round 9
// speedup vs baseline: 1.4498x; 1.4498x over previous
#include <cuda_runtime.h>
#include <math.h>

// ---------------------------------------------------------------------------
// Problem constants (fixed by dataset; runtime sizes still read from in_sizes)
// ---------------------------------------------------------------------------
#define D_C       128
#define PITCH     132          // z_sh row pitch (floats)
#define PITCHI    264          // paired-I row pitch (floats)
#define MAX_ITEMS 200000
#define MAX_USERS 100000
#define MAX_EII   3200000
#define MAX_EUI   1600000
#define MAX_EDGES (3 * MAX_EII + MAX_EUI)          // 11.2M
#define MAX_ROWS  (3 * MAX_ITEMS + MAX_USERS)      // 700K logical output rows
#define SCAN_CHUNK 4096
#define MAX_PARTS ((MAX_ROWS + SCAN_CHUNK - 1) / SCAN_CHUNK + 1)

// Static device scratch (no allocs allowed).
__device__ float g_nb  [(size_t)3 * MAX_ITEMS * D_C];   // 3 item->item aggregates
__device__ int2  g_bpk [MAX_EDGES];                     // binned (src, val-bits)
__device__ int   g_cnt [MAX_ROWS];                      // per-row edge counts
__device__ int   g_off [MAX_ROWS + 1];                  // CSR row offsets
__device__ int   g_cur [MAX_ROWS];                      // scatter cursors
__device__ int   g_part[MAX_PARTS];                     // scan block partials

// ---------------------------------------------------------------------------
// Pass 1: histogram of destination rows (4 edges / thread, int4 loads)
// (unchanged across rounds — serves as the DVFS clock canary in ncu)
// ---------------------------------------------------------------------------
__global__ void hist_kernel(const int* __restrict__ dst, int nE, int base,
                            int* __restrict__ cnt)
{
    int i0 = (blockIdx.x * blockDim.x + threadIdx.x) * 4;
    if (i0 + 3 < nE) {
        int4 d = *reinterpret_cast<const int4*>(dst + i0);
        atomicAdd(&cnt[base + d.x], 1);
        atomicAdd(&cnt[base + d.y], 1);
        atomicAdd(&cnt[base + d.z], 1);
        atomicAdd(&cnt[base + d.w], 1);
    } else {
        for (int j = i0; j < nE; j++) atomicAdd(&cnt[base + dst[j]], 1);
    }
}

// ---------------------------------------------------------------------------
// Pass 2a: per-block sums (4096 elements / block)
// ---------------------------------------------------------------------------
__global__ void __launch_bounds__(1024)
block_sum_kernel(const int* __restrict__ cnt, int* __restrict__ part, int N)
{
    __shared__ int ws[32];
    const int tid = threadIdx.x, lane = tid & 31, wid = tid >> 5;
    int idx = blockIdx.x * SCAN_CHUNK + tid * 4;
    int t = 0;
    if (idx + 3 < N) {
        int4 v = *reinterpret_cast<const int4*>(cnt + idx);
        t = v.x + v.y + v.z + v.w;
    } else {
        for (int j = idx; j < min(idx + 4, N); j++) t += cnt[j];
    }
#pragma unroll
    for (int o = 16; o > 0; o >>= 1) t += __shfl_xor_sync(0xffffffffu, t, o);
    if (lane == 0) ws[wid] = t;
    __syncthreads();
    if (wid == 0) {
        int u = ws[lane];
#pragma unroll
        for (int o = 16; o > 0; o >>= 1) u += __shfl_xor_sync(0xffffffffu, u, o);
        if (lane == 0) part[blockIdx.x] = u;
    }
}

// ---------------------------------------------------------------------------
// Pass 2b: exclusive scan of the (<=1024) block partials; writes off[N]
// ---------------------------------------------------------------------------
__global__ void __launch_bounds__(1024)
part_scan_kernel(int* __restrict__ part, int nparts, int* __restrict__ off_total)
{
    __shared__ int wtot[32];
    const int tid = threadIdx.x, lane = tid & 31, wid = tid >> 5;
    int v = (tid < nparts) ? part[tid] : 0;
    int incl = v;
#pragma unroll
    for (int o = 1; o < 32; o <<= 1) {
        int u = __shfl_up_sync(0xffffffffu, incl, o);
        if (lane >= o) incl += u;
    }
    if (lane == 31) wtot[wid] = incl;
    __syncthreads();
    if (wid == 0) {
        int w = wtot[lane];
        int wi = w;
#pragma unroll
        for (int o = 1; o < 32; o <<= 1) {
            int u = __shfl_up_sync(0xffffffffu, wi, o);
            if (lane >= o) wi += u;
        }
        wtot[lane] = wi - w;     // exclusive warp offsets
    }
    __syncthreads();
    int excl = wtot[wid] + incl - v;
    if (tid < nparts) part[tid] = excl;
    if (tid == nparts - 1) *off_total = excl + v;   // off[N] = grand total
}

// ---------------------------------------------------------------------------
// Pass 2c: final scan — local 4096-chunk scan + per-block carry from part[]
// ---------------------------------------------------------------------------
__global__ void __launch_bounds__(1024)
scan_final_kernel(const int* __restrict__ cnt, const int* __restrict__ part,
                  int* __restrict__ off, int* __restrict__ cur, int N)
{
    __shared__ int wtot[32];
    __shared__ int wexcl[32];
    const int tid = threadIdx.x, lane = tid & 31, wid = tid >> 5;
    int idx = blockIdx.x * SCAN_CHUNK + tid * 4;

    int4 v = make_int4(0, 0, 0, 0);
    if (idx + 3 < N)      v = *reinterpret_cast<const int4*>(cnt + idx);
    else if (idx < N) {
        v.x = cnt[idx];
        if (idx + 1 < N) v.y = cnt[idx + 1];
        if (idx + 2 < N) v.z = cnt[idx + 2];
    }
    int t0 = v.x, t1 = t0 + v.y, t2 = t1 + v.z, t3 = t2 + v.w;

    int incl = t3;
#pragma unroll
    for (int o = 1; o < 32; o <<= 1) {
        int u = __shfl_up_sync(0xffffffffu, incl, o);
        if (lane >= o) incl += u;
    }
    int thr_excl = incl - t3;
    if (lane == 31) wtot[wid] = incl;
    __syncthreads();
    if (wid == 0) {
        int w = wtot[lane];
        int wi = w;
#pragma unroll
        for (int o = 1; o < 32; o <<= 1) {
            int u = __shfl_up_sync(0xffffffffu, wi, o);
            if (lane >= o) wi += u;
        }
        wexcl[lane] = wi - w;
    }
    __syncthreads();
    int ex = part[blockIdx.x] + wexcl[wid] + thr_excl;
    if (idx + 3 < N) {
        int4 o4 = make_int4(ex, ex + t0, ex + t1, ex + t2);
        *reinterpret_cast<int4*>(off + idx) = o4;
        *reinterpret_cast<int4*>(cur + idx) = o4;
    } else if (idx < N) {
        off[idx] = ex;           cur[idx] = ex;
        if (idx + 1 < N) { off[idx + 1] = ex + t0; cur[idx + 1] = ex + t0; }
        if (idx + 2 < N) { off[idx + 2] = ex + t1; cur[idx + 2] = ex + t1; }
    }
}

// ---------------------------------------------------------------------------
// Pass 3: scatter edges into destination bins — ONE packed 8B write per edge
// ---------------------------------------------------------------------------
__global__ void scatter_kernel(const int* __restrict__ src,
                               const int* __restrict__ dst,
                               const float* __restrict__ val,
                               int nE, int base, int* __restrict__ cur,
                               int2* __restrict__ bpk)
{
    int i = blockIdx.x * blockDim.x + threadIdx.x;
    if (i < nE) {
        int d   = dst[i];
        int pos = atomicAdd(&cur[base + d], 1);
        bpk[pos] = make_int2(src[i], __float_as_int(val[i]));
    }
}

// ---------------------------------------------------------------------------
// Pass 4: gather-accumulate. One warp per output row; 2-way grouped x loads
// (MLP=2, two accumulators — lower register pressure than the 4-way variant);
// single 512B store per row, no atomics, no output memset.
// ---------------------------------------------------------------------------
__global__ void __launch_bounds__(256)
gather_kernel(const int* __restrict__ off,
              const int2* __restrict__ bpk,
              const float* __restrict__ x,
              float* __restrict__ nb, float* __restrict__ uemb,
              int n3, int nrows)
{
    int w = (blockIdx.x * blockDim.x + threadIdx.x) >> 5;
    if (w >= nrows) return;
    const int lane = threadIdx.x & 31;

    unsigned long long pol;
    asm("createpolicy.fractional.L2::evict_last.b64 %0, 1.0;" : "=l"(pol));

    int beg = __ldg(off + w);
    int end = __ldg(off + w + 1);

    float4 a0 = make_float4(0.f, 0.f, 0.f, 0.f);
    float4 a1 = make_float4(0.f, 0.f, 0.f, 0.f);

#define XLOAD(T, SRC)                                                          \
    {                                                                          \
        const float* xp = x + (size_t)(SRC) * D_C + lane * 4;                  \
        asm volatile("ld.global.nc.L2::cache_hint.v4.f32 {%0,%1,%2,%3}, [%4], %5;" \
                     : "=f"(T.x), "=f"(T.y), "=f"(T.z), "=f"(T.w)              \
                     : "l"(xp), "l"(pol));                                     \
    }
#define XFMA(A, T, V)                                                          \
    A.x = fmaf(T.x, V, A.x); A.y = fmaf(T.y, V, A.y);                          \
    A.z = fmaf(T.z, V, A.z); A.w = fmaf(T.w, V, A.w);

    for (int p = beg; p < end; p += 32) {
        int n = min(32, end - p);
        int2 pk = make_int2(0, 0);
        if (lane < n) pk = __ldg(bpk + p + lane);

        int e = 0;
        for (; e + 2 <= n; e += 2) {
            int   s0 = __shfl_sync(0xffffffffu, pk.x, e);
            int   s1 = __shfl_sync(0xffffffffu, pk.x, e + 1);
            float v0 = __int_as_float(__shfl_sync(0xffffffffu, pk.y, e));
            float v1 = __int_as_float(__shfl_sync(0xffffffffu, pk.y, e + 1));
            float4 t0, t1;
            XLOAD(t0, s0); XLOAD(t1, s1);
            XFMA(a0, t0, v0); XFMA(a1, t1, v1);
        }
        if (e < n) {
            int   se = __shfl_sync(0xffffffffu, pk.x, e);
            float ve = __int_as_float(__shfl_sync(0xffffffffu, pk.y, e));
            float4 t; XLOAD(t, se); XFMA(a0, t, ve);
        }
    }
#undef XLOAD
#undef XFMA

    a0.x += a1.x; a0.y += a1.y; a0.z += a1.z; a0.w += a1.w;

    float* o = (w < n3) ? (nb + (size_t)w * D_C)
                        : (uemb + (size_t)(w - n3) * D_C);
    *reinterpret_cast<float4*>(o + lane * 4) = a0;
}

// ---------------------------------------------------------------------------
// Score + combine kernel: 64 rows / block, 512 threads, 2 blocks/SM.
// ---------------------------------------------------------------------------
__device__ __forceinline__ unsigned long long ld_u64_smem(const float* p)
{
    return *reinterpret_cast<const unsigned long long*>(p);
}

__global__ void __launch_bounds__(512, 2)
score_kernel(const float* __restrict__ x,
             const float* __restrict__ nb0,
             const float* __restrict__ nb1,
             const float* __restrict__ nb2,
             const float* __restrict__ I0,
             const float* __restrict__ I1,
             const float* __restrict__ I2,
             float* __restrict__ out,
             int nrows)
{
    extern __shared__ float sm[];
    float* I_sh = sm;                              // 64 * PITCHI (paired k rows)
    float* z_sh = sm + 64 * PITCHI;                // 64 * PITCH
    float* s_sh = sm + 64 * PITCHI + 64 * PITCH;   // 3 * 64

    const int tid  = threadIdx.x;
    const int lane = tid & 31;
    const int wid  = tid >> 5;                     // 16 warps
    const int r0   = wid << 2;                     // 4 rows per warp
    const int row0 = blockIdx.x * 64;
    const int rows = min(64, nrows - row0);

    const float4* xg = reinterpret_cast<const float4*>(x);

#pragma unroll 1
    for (int rel = 0; rel < 3; rel++) {
        const float* nbp = (rel == 0) ? nb0 : (rel == 1) ? nb1 : nb2;
        const float* Ip  = (rel == 0) ? I0  : (rel == 1) ? I1  : I2;

        const float4* Ig = reinterpret_cast<const float4*>(Ip);
        for (int idx = tid; idx < 64 * 32; idx += 512) {
            int p  = idx >> 5;
            int j4 = idx & 31;
            float4 ae = Ig[(2 * p)     * 32 + j4];
            float4 ao = Ig[(2 * p + 1) * 32 + j4];
            float* wp = &I_sh[p * PITCHI + (j4 << 3)];
            *reinterpret_cast<float4*>(wp)     = make_float4(ae.x, ao.x, ae.y, ao.y);
            *reinterpret_cast<float4*>(wp + 4) = make_float4(ae.z, ao.z, ae.w, ao.w);
        }
        const float4* ng = reinterpret_cast<const float4*>(nbp);
        for (int idx = tid; idx < 64 * 32; idx += 512) {
            int r  = idx >> 5;
            int k4 = idx & 31;
            float4 zv = make_float4(0.f, 0.f, 0.f, 0.f);
            if (r < rows) {
                size_t offr = (size_t)(row0 + r) * 32 + k4;
                float4 av = xg[offr];
                float4 bv = ng[offr];
                zv.x = av.x * bv.x; zv.y = av.y * bv.y;
                zv.z = av.z * bv.z; zv.w = av.w * bv.w;
            }
            *reinterpret_cast<float4*>(&z_sh[r * PITCH + (k4 << 2)]) = zv;
        }
        __syncthreads();

        unsigned long long acc[4][4];
#pragma unroll
        for (int r = 0; r < 4; r++)
#pragma unroll
            for (int c = 0; c < 4; c++) acc[r][c] = 0ull;

        for (int p = 0; p < 64; p++) {
            unsigned long long zp[4];
#pragma unroll
            for (int r = 0; r < 4; r++)
                zp[r] = ld_u64_smem(&z_sh[(r0 + r) * PITCH + 2 * p]);
#pragma unroll
            for (int c = 0; c < 4; c++) {
                unsigned long long bp =
                    ld_u64_smem(&I_sh[p * PITCHI + ((lane + 32 * c) << 1)]);
#pragma unroll
                for (int r = 0; r < 4; r++)
                    asm("fma.rn.f32x2 %0, %1, %2, %0;"
                        : "+l"(acc[r][c]) : "l"(zp[r]), "l"(bp));
            }
        }

#pragma unroll
        for (int r = 0; r < 4; r++) {
            float rs = 0.f;
#pragma unroll
            for (int c = 0; c < 4; c++) {
                float lo = __int_as_float((int)(acc[r][c] & 0xffffffffull));
                float hi = __int_as_float((int)(acc[r][c] >> 32));
                float h  = lo + hi;
                rs += (h >= 0.f) ? h : 0.2f * h;
            }
#pragma unroll
            for (int o = 16; o > 0; o >>= 1)
                rs += __shfl_xor_sync(0xffffffffu, rs, o);
            if (lane == 0)
                s_sh[rel * 64 + r0 + r] = rs * 0.08838834764831845f; // 1/sqrt(128)
        }
        __syncthreads();
    }

    const float4* n0g = reinterpret_cast<const float4*>(nb0);
    const float4* n1g = reinterpret_cast<const float4*>(nb1);
    const float4* n2g = reinterpret_cast<const float4*>(nb2);
    float4* og = reinterpret_cast<float4*>(out);

    for (int idx = tid; idx < 64 * 32; idx += 512) {
        int r  = idx >> 5;
        int c4 = idx & 31;
        if (r >= rows) continue;
        float s0 = s_sh[r];
        float s1 = s_sh[64 + r];
        float s2 = s_sh[128 + r];
        float m  = fmaxf(s0, fmaxf(s1, s2));
        float e0 = __expf(s0 - m);
        float e1 = __expf(s1 - m);
        float e2 = __expf(s2 - m);
        float inv = 1.f / (e0 + e1 + e2);
        float w0 = e0 * inv, w1 = e1 * inv, w2 = e2 * inv;

        size_t offr = (size_t)(row0 + r) * 32 + c4;
        float4 av = n0g[offr], bv = n1g[offr], cv = n2g[offr];
        float4 o;
        o.x = w0 * av.x + w1 * bv.x + w2 * cv.x;
        o.y = w0 * av.y + w1 * bv.y + w2 * cv.y;
        o.z = w0 * av.z + w1 * bv.z + w2 * cv.z;
        o.w = w0 * av.w + w1 * bv.w + w2 * cv.w;
        og[offr] = o;
    }
}

// ---------------------------------------------------------------------------
// Launch
// ---------------------------------------------------------------------------
extern "C" void kernel_launch(void* const* d_in, const int* in_sizes, int n_in,
                              void* d_out, int out_size)
{
    int base = (in_sizes[0] == 1) ? 1 : 0;

    const float* x      = (const float*)d_in[base + 0];
    const int*   srcs[4] = { (const int*)d_in[base + 1], (const int*)d_in[base + 4],
                             (const int*)d_in[base + 7], (const int*)d_in[base + 10] };
    const int*   dsts[4] = { (const int*)d_in[base + 2], (const int*)d_in[base + 5],
                             (const int*)d_in[base + 8], (const int*)d_in[base + 11] };
    const float* vals[4] = { (const float*)d_in[base + 3], (const float*)d_in[base + 6],
                             (const float*)d_in[base + 9], (const float*)d_in[base + 12] };
    const float* I0     = (const float*)d_in[base + 13];
    const float* I1     = (const float*)d_in[base + 14];
    const float* I2     = (const float*)d_in[base + 15];

    int n_items = in_sizes[base + 0] / D_C;
    int nE[4]   = { in_sizes[base + 1], in_sizes[base + 4],
                    in_sizes[base + 7], in_sizes[base + 10] };
    int n_users = out_size / D_C - n_items;
    int n3      = 3 * n_items;
    int nrows   = n3 + n_users;

    float* out_f    = (float*)d_out;
    float* u_emb    = out_f;                          // tuple order: (u_emb, neighbor)
    float* neighbor = out_f + (size_t)n_users * D_C;

    float *nb_base; int2 *bpk; int *cnt, *off, *cur, *part;
    cudaGetSymbolAddress((void**)&nb_base, g_nb);
    cudaGetSymbolAddress((void**)&bpk,     g_bpk);
    cudaGetSymbolAddress((void**)&cnt,     g_cnt);
    cudaGetSymbolAddress((void**)&off,     g_off);
    cudaGetSymbolAddress((void**)&cur,     g_cur);
    cudaGetSymbolAddress((void**)&part,    g_part);

    float* nb0 = nb_base;
    float* nb1 = nb_base + (size_t)n_items * D_C;
    float* nb2 = nb_base + (size_t)2 * n_items * D_C;

    // --- build CSR bins -----------------------------------------------------
    cudaMemsetAsync(cnt, 0, (size_t)nrows * sizeof(int), 0);
    for (int r = 0; r < 4; r++) {
        int b = (r < 3) ? r * n_items : n3;
        int g = ((nE[r] + 3) / 4 + 255) / 256;
        hist_kernel<<<g, 256>>>(dsts[r], nE[r], b, cnt);
    }
    int nparts = (nrows + SCAN_CHUNK - 1) / SCAN_CHUNK;
    block_sum_kernel<<<nparts, 1024>>>(cnt, part, nrows);
    part_scan_kernel<<<1, 1024>>>(part, nparts, off + nrows);
    scan_final_kernel<<<nparts, 1024>>>(cnt, part, off, cur, nrows);
    for (int r = 0; r < 4; r++) {
        int b = (r < 3) ? r * n_items : n3;
        int g = (nE[r] + 255) / 256;
        scatter_kernel<<<g, 256>>>(srcs[r], dsts[r], vals[r], nE[r], b, cur, bpk);
    }

    // --- gather-accumulate: writes nb0..2 and u_emb (no memset needed) -------
    {
        int g = ((nrows * 32) + 255) / 256;
        gather_kernel<<<g, 256>>>(off, bpk, x, nb_base, u_emb, n3, nrows);
    }

    // --- score + combine ------------------------------------------------------
    const int smem_bytes = (64 * PITCHI + 64 * PITCH + 3 * 64) * (int)sizeof(float);
    cudaFuncSetAttribute(score_kernel,
                         cudaFuncAttributeMaxDynamicSharedMemorySize, smem_bytes);
    int nblocks = (n_items + 63) / 64;
    score_kernel<<<nblocks, 512, smem_bytes>>>(x, nb0, nb1, nb2, I0, I1, I2,
                                               neighbor, n_items);
}

// round 10
// speedup vs baseline: 1.4842x; 1.0237x over previous
#include <cuda_runtime.h>
#include <math.h>

// ---------------------------------------------------------------------------
// Problem constants (fixed by dataset; runtime sizes still read from in_sizes)
// ---------------------------------------------------------------------------
#define D_C       128
#define PITCH     132          // z_sh row pitch (floats)
#define PITCHI    264          // paired-I row pitch (floats)
#define MAX_ITEMS 200000
#define MAX_USERS 100000
#define MAX_EII   3200000
#define MAX_EUI   1600000
#define MAX_EDGES (3 * MAX_EII + MAX_EUI)          // 11.2M
#define MAX_ROWS  (3 * MAX_ITEMS + MAX_USERS)      // 700K logical output rows
#define SCAN_CHUNK 4096
#define MAX_PARTS ((MAX_ROWS + SCAN_CHUNK - 1) / SCAN_CHUNK + 1)

// Static device scratch (no allocs allowed).
__device__ float g_nb  [(size_t)3 * MAX_ITEMS * D_C];   // 3 item->item aggregates
__device__ int2  g_bpk [MAX_EDGES];                     // binned (src, val-bits)
__device__ int   g_cnt [MAX_ROWS];                      // per-row edge counts
__device__ int   g_off [MAX_ROWS + 1];                  // CSR row offsets
__device__ int   g_cur [MAX_ROWS];                      // scatter cursors
__device__ int   g_part[MAX_PARTS];                     // scan block partials

// ---------------------------------------------------------------------------
// Pass 1: histogram of destination rows (4 edges / thread, int4 loads)
// (unchanged across rounds — serves as the DVFS clock canary in ncu)
// ---------------------------------------------------------------------------
__global__ void hist_kernel(const int* __restrict__ dst, int nE, int base,
                            int* __restrict__ cnt)
{
    int i0 = (blockIdx.x * blockDim.x + threadIdx.x) * 4;
    if (i0 + 3 < nE) {
        int4 d = *reinterpret_cast<const int4*>(dst + i0);
        atomicAdd(&cnt[base + d.x], 1);
        atomicAdd(&cnt[base + d.y], 1);
        atomicAdd(&cnt[base + d.z], 1);
        atomicAdd(&cnt[base + d.w], 1);
    } else {
        for (int j = i0; j < nE; j++) atomicAdd(&cnt[base + dst[j]], 1);
    }
}

// ---------------------------------------------------------------------------
// Pass 2a: per-block sums (4096 elements / block)
// ---------------------------------------------------------------------------
__global__ void __launch_bounds__(1024)
block_sum_kernel(const int* __restrict__ cnt, int* __restrict__ part, int N)
{
    __shared__ int ws[32];
    const int tid = threadIdx.x, lane = tid & 31, wid = tid >> 5;
    int idx = blockIdx.x * SCAN_CHUNK + tid * 4;
    int t = 0;
    if (idx + 3 < N) {
        int4 v = *reinterpret_cast<const int4*>(cnt + idx);
        t = v.x + v.y + v.z + v.w;
    } else {
        for (int j = idx; j < min(idx + 4, N); j++) t += cnt[j];
    }
#pragma unroll
    for (int o = 16; o > 0; o >>= 1) t += __shfl_xor_sync(0xffffffffu, t, o);
    if (lane == 0) ws[wid] = t;
    __syncthreads();
    if (wid == 0) {
        int u = ws[lane];
#pragma unroll
        for (int o = 16; o > 0; o >>= 1) u += __shfl_xor_sync(0xffffffffu, u, o);
        if (lane == 0) part[blockIdx.x] = u;
    }
}

// ---------------------------------------------------------------------------
// Pass 2b: exclusive scan of the (<=1024) block partials; writes off[N]
// ---------------------------------------------------------------------------
__global__ void __launch_bounds__(1024)
part_scan_kernel(int* __restrict__ part, int nparts, int* __restrict__ off_total)
{
    __shared__ int wtot[32];
    const int tid = threadIdx.x, lane = tid & 31, wid = tid >> 5;
    int v = (tid < nparts) ? part[tid] : 0;
    int incl = v;
#pragma unroll
    for (int o = 1; o < 32; o <<= 1) {
        int u = __shfl_up_sync(0xffffffffu, incl, o);
        if (lane >= o) incl += u;
    }
    if (lane == 31) wtot[wid] = incl;
    __syncthreads();
    if (wid == 0) {
        int w = wtot[lane];
        int wi = w;
#pragma unroll
        for (int o = 1; o < 32; o <<= 1) {
            int u = __shfl_up_sync(0xffffffffu, wi, o);
            if (lane >= o) wi += u;
        }
        wtot[lane] = wi - w;     // exclusive warp offsets
    }
    __syncthreads();
    int excl = wtot[wid] + incl - v;
    if (tid < nparts) part[tid] = excl;
    if (tid == nparts - 1) *off_total = excl + v;   // off[N] = grand total
}

// ---------------------------------------------------------------------------
// Pass 2c: final scan — local 4096-chunk scan + per-block carry from part[]
// ---------------------------------------------------------------------------
__global__ void __launch_bounds__(1024)
scan_final_kernel(const int* __restrict__ cnt, const int* __restrict__ part,
                  int* __restrict__ off, int* __restrict__ cur, int N)
{
    __shared__ int wtot[32];
    __shared__ int wexcl[32];
    const int tid = threadIdx.x, lane = tid & 31, wid = tid >> 5;
    int idx = blockIdx.x * SCAN_CHUNK + tid * 4;

    int4 v = make_int4(0, 0, 0, 0);
    if (idx + 3 < N)      v = *reinterpret_cast<const int4*>(cnt + idx);
    else if (idx < N) {
        v.x = cnt[idx];
        if (idx + 1 < N) v.y = cnt[idx + 1];
        if (idx + 2 < N) v.z = cnt[idx + 2];
    }
    int t0 = v.x, t1 = t0 + v.y, t2 = t1 + v.z, t3 = t2 + v.w;

    int incl = t3;
#pragma unroll
    for (int o = 1; o < 32; o <<= 1) {
        int u = __shfl_up_sync(0xffffffffu, incl, o);
        if (lane >= o) incl += u;
    }
    int thr_excl = incl - t3;
    if (lane == 31) wtot[wid] = incl;
    __syncthreads();
    if (wid == 0) {
        int w = wtot[lane];
        int wi = w;
#pragma unroll
        for (int o = 1; o < 32; o <<= 1) {
            int u = __shfl_up_sync(0xffffffffu, wi, o);
            if (lane >= o) wi += u;
        }
        wexcl[lane] = wi - w;
    }
    __syncthreads();
    int ex = part[blockIdx.x] + wexcl[wid] + thr_excl;
    if (idx + 3 < N) {
        int4 o4 = make_int4(ex, ex + t0, ex + t1, ex + t2);
        *reinterpret_cast<int4*>(off + idx) = o4;
        *reinterpret_cast<int4*>(cur + idx) = o4;
    } else if (idx < N) {
        off[idx] = ex;           cur[idx] = ex;
        if (idx + 1 < N) { off[idx + 1] = ex + t0; cur[idx + 1] = ex + t0; }
        if (idx + 2 < N) { off[idx + 2] = ex + t1; cur[idx + 2] = ex + t1; }
    }
}

// ---------------------------------------------------------------------------
// Pass 3: scatter edges into destination bins — ONE packed 8B write per edge
// ---------------------------------------------------------------------------
__global__ void scatter_kernel(const int* __restrict__ src,
                               const int* __restrict__ dst,
                               const float* __restrict__ val,
                               int nE, int base, int* __restrict__ cur,
                               int2* __restrict__ bpk)
{
    int i = blockIdx.x * blockDim.x + threadIdx.x;
    if (i < nE) {
        int d   = dst[i];
        int pos = atomicAdd(&cur[base + d], 1);
        bpk[pos] = make_int2(src[i], __float_as_int(val[i]));
    }
}

// ---------------------------------------------------------------------------
// Pass 4: gather-accumulate. One warp per output row; 2-way grouped x loads
// (MLP=2); single 512B store per row, no atomics, no output memset.
// ---------------------------------------------------------------------------
__global__ void __launch_bounds__(256)
gather_kernel(const int* __restrict__ off,
              const int2* __restrict__ bpk,
              const float* __restrict__ x,
              float* __restrict__ nb, float* __restrict__ uemb,
              int n3, int nrows)
{
    int w = (blockIdx.x * blockDim.x + threadIdx.x) >> 5;
    if (w >= nrows) return;
    const int lane = threadIdx.x & 31;

    unsigned long long pol;
    asm("createpolicy.fractional.L2::evict_last.b64 %0, 1.0;" : "=l"(pol));

    int beg = __ldg(off + w);
    int end = __ldg(off + w + 1);

    float4 a0 = make_float4(0.f, 0.f, 0.f, 0.f);
    float4 a1 = make_float4(0.f, 0.f, 0.f, 0.f);

#define XLOAD(T, SRC)                                                          \
    {                                                                          \
        const float* xp = x + (size_t)(SRC) * D_C + lane * 4;                  \
        asm volatile("ld.global.nc.L2::cache_hint.v4.f32 {%0,%1,%2,%3}, [%4], %5;" \
                     : "=f"(T.x), "=f"(T.y), "=f"(T.z), "=f"(T.w)              \
                     : "l"(xp), "l"(pol));                                     \
    }
#define XFMA(A, T, V)                                                          \
    A.x = fmaf(T.x, V, A.x); A.y = fmaf(T.y, V, A.y);                          \
    A.z = fmaf(T.z, V, A.z); A.w = fmaf(T.w, V, A.w);

    for (int p = beg; p < end; p += 32) {
        int n = min(32, end - p);
        int2 pk = make_int2(0, 0);
        if (lane < n) pk = __ldg(bpk + p + lane);

        int e = 0;
        for (; e + 2 <= n; e += 2) {
            int   s0 = __shfl_sync(0xffffffffu, pk.x, e);
            int   s1 = __shfl_sync(0xffffffffu, pk.x, e + 1);
            float v0 = __int_as_float(__shfl_sync(0xffffffffu, pk.y, e));
            float v1 = __int_as_float(__shfl_sync(0xffffffffu, pk.y, e + 1));
            float4 t0, t1;
            XLOAD(t0, s0); XLOAD(t1, s1);
            XFMA(a0, t0, v0); XFMA(a1, t1, v1);
        }
        if (e < n) {
            int   se = __shfl_sync(0xffffffffu, pk.x, e);
            float ve = __int_as_float(__shfl_sync(0xffffffffu, pk.y, e));
            float4 t; XLOAD(t, se); XFMA(a0, t, ve);
        }
    }
#undef XLOAD
#undef XFMA

    a0.x += a1.x; a0.y += a1.y; a0.z += a1.z; a0.w += a1.w;

    float* o = (w < n3) ? (nb + (size_t)w * D_C)
                        : (uemb + (size_t)(w - n3) * D_C);
    *reinterpret_cast<float4*>(o + lane * 4) = a0;
}

// ---------------------------------------------------------------------------
// Score + combine kernel v3: 256 threads (8 warps), 64 rows/block,
// 8 rows PER WARP. Rationale: the I-tile LDS.64 loads amortize over rows —
// at 8 rows/warp the inner loop is 8 z-broadcasts + 4 I LDS.64 (16 crossbar
// cycles) against 32 FFMA2 (16 issue cycles): fma-bound instead of the old
// 4-rows/warp variant's 12:8 LDS-bound ratio. smem 102KB -> 2 blocks/SM.
// ---------------------------------------------------------------------------
__device__ __forceinline__ unsigned long long ld_u64_smem(const float* p)
{
    return *reinterpret_cast<const unsigned long long*>(p);
}

__global__ void __launch_bounds__(256, 2)
score_kernel(const float* __restrict__ x,
             const float* __restrict__ nb0,
             const float* __restrict__ nb1,
             const float* __restrict__ nb2,
             const float* __restrict__ I0,
             const float* __restrict__ I1,
             const float* __restrict__ I2,
             float* __restrict__ out,
             int nrows)
{
    extern __shared__ float sm[];
    float* I_sh = sm;                              // 64 * PITCHI (paired k rows)
    float* z_sh = sm + 64 * PITCHI;                // 64 * PITCH
    float* s_sh = sm + 64 * PITCHI + 64 * PITCH;   // 3 * 64

    const int tid  = threadIdx.x;
    const int lane = tid & 31;
    const int wid  = tid >> 5;                     // 8 warps
    const int r0   = wid << 3;                     // 8 rows per warp
    const int row0 = blockIdx.x * 64;
    const int rows = min(64, nrows - row0);

    const float4* xg = reinterpret_cast<const float4*>(x);

#pragma unroll 1
    for (int rel = 0; rel < 3; rel++) {
        const float* nbp = (rel == 0) ? nb0 : (rel == 1) ? nb1 : nb2;
        const float* Ip  = (rel == 0) ? I0  : (rel == 1) ? I1  : I2;

        // ---- stage I as k-pair-interleaved rows -----------------------------
        const float4* Ig = reinterpret_cast<const float4*>(Ip);
        for (int idx = tid; idx < 64 * 32; idx += 256) {
            int p  = idx >> 5;
            int j4 = idx & 31;
            float4 ae = Ig[(2 * p)     * 32 + j4];
            float4 ao = Ig[(2 * p + 1) * 32 + j4];
            float* wp = &I_sh[p * PITCHI + (j4 << 3)];
            *reinterpret_cast<float4*>(wp)     = make_float4(ae.x, ao.x, ae.y, ao.y);
            *reinterpret_cast<float4*>(wp + 4) = make_float4(ae.z, ao.z, ae.w, ao.w);
        }
        // ---- stage z = x * nb ------------------------------------------------
        const float4* ng = reinterpret_cast<const float4*>(nbp);
        for (int idx = tid; idx < 64 * 32; idx += 256) {
            int r  = idx >> 5;
            int k4 = idx & 31;
            float4 zv = make_float4(0.f, 0.f, 0.f, 0.f);
            if (r < rows) {
                size_t offr = (size_t)(row0 + r) * 32 + k4;
                float4 av = xg[offr];
                float4 bv = ng[offr];
                zv.x = av.x * bv.x; zv.y = av.y * bv.y;
                zv.z = av.z * bv.z; zv.w = av.w * bv.w;
            }
            *reinterpret_cast<float4*>(&z_sh[r * PITCH + (k4 << 2)]) = zv;
        }
        __syncthreads();

        // ---- register-tiled matvec: 8 rows x 4 interleaved cols --------------
        unsigned long long acc[8][4];
#pragma unroll
        for (int r = 0; r < 8; r++)
#pragma unroll
            for (int c = 0; c < 4; c++) acc[r][c] = 0ull;

        for (int p = 0; p < 64; p++) {
            unsigned long long zp[8];
#pragma unroll
            for (int r = 0; r < 8; r++)        // broadcast LDS.64: {z[2p], z[2p+1]}
                zp[r] = ld_u64_smem(&z_sh[(r0 + r) * PITCH + 2 * p]);
#pragma unroll
            for (int c = 0; c < 4; c++) {
                unsigned long long bp =
                    ld_u64_smem(&I_sh[p * PITCHI + ((lane + 32 * c) << 1)]);
#pragma unroll
                for (int r = 0; r < 8; r++)
                    asm("fma.rn.f32x2 %0, %1, %2, %0;"
                        : "+l"(acc[r][c]) : "l"(zp[r]), "l"(bp));
            }
        }

        // ---- leaky_relu + column sum + warp reduce ---------------------------
#pragma unroll
        for (int r = 0; r < 8; r++) {
            float rs = 0.f;
#pragma unroll
            for (int c = 0; c < 4; c++) {
                float lo = __int_as_float((int)(acc[r][c] & 0xffffffffull));
                float hi = __int_as_float((int)(acc[r][c] >> 32));
                float h  = lo + hi;
                rs += (h >= 0.f) ? h : 0.2f * h;
            }
#pragma unroll
            for (int o = 16; o > 0; o >>= 1)
                rs += __shfl_xor_sync(0xffffffffu, rs, o);
            if (lane == 0)
                s_sh[rel * 64 + r0 + r] = rs * 0.08838834764831845f; // 1/sqrt(128)
        }
        __syncthreads();
    }

    // ---- softmax over relations + weighted combine ---------------------------
    const float4* n0g = reinterpret_cast<const float4*>(nb0);
    const float4* n1g = reinterpret_cast<const float4*>(nb1);
    const float4* n2g = reinterpret_cast<const float4*>(nb2);
    float4* og = reinterpret_cast<float4*>(out);

    for (int idx = tid; idx < 64 * 32; idx += 256) {
        int r  = idx >> 5;
        int c4 = idx & 31;
        if (r >= rows) continue;
        float s0 = s_sh[r];
        float s1 = s_sh[64 + r];
        float s2 = s_sh[128 + r];
        float m  = fmaxf(s0, fmaxf(s1, s2));
        float e0 = __expf(s0 - m);
        float e1 = __expf(s1 - m);
        float e2 = __expf(s2 - m);
        float inv = 1.f / (e0 + e1 + e2);
        float w0 = e0 * inv, w1 = e1 * inv, w2 = e2 * inv;

        size_t offr = (size_t)(row0 + r) * 32 + c4;
        float4 av = n0g[offr], bv = n1g[offr], cv = n2g[offr];
        float4 o;
        o.x = w0 * av.x + w1 * bv.x + w2 * cv.x;
        o.y = w0 * av.y + w1 * bv.y + w2 * cv.y;
        o.z = w0 * av.z + w1 * bv.z + w2 * cv.z;
        o.w = w0 * av.w + w1 * bv.w + w2 * cv.w;
        og[offr] = o;
    }
}

// ---------------------------------------------------------------------------
// Launch
// ---------------------------------------------------------------------------
extern "C" void kernel_launch(void* const* d_in, const int* in_sizes, int n_in,
                              void* d_out, int out_size)
{
    int base = (in_sizes[0] == 1) ? 1 : 0;

    const float* x      = (const float*)d_in[base + 0];
    const int*   srcs[4] = { (const int*)d_in[base + 1], (const int*)d_in[base + 4],
                             (const int*)d_in[base + 7], (const int*)d_in[base + 10] };
    const int*   dsts[4] = { (const int*)d_in[base + 2], (const int*)d_in[base + 5],
                             (const int*)d_in[base + 8], (const int*)d_in[base + 11] };
    const float* vals[4] = { (const float*)d_in[base + 3], (const float*)d_in[base + 6],
                             (const float*)d_in[base + 9], (const float*)d_in[base + 12] };
    const float* I0     = (const float*)d_in[base + 13];
    const float* I1     = (const float*)d_in[base + 14];
    const float* I2     = (const float*)d_in[base + 15];

    int n_items = in_sizes[base + 0] / D_C;
    int nE[4]   = { in_sizes[base + 1], in_sizes[base + 4],
                    in_sizes[base + 7], in_sizes[base + 10] };
    int n_users = out_size / D_C - n_items;
    int n3      = 3 * n_items;
    int nrows   = n3 + n_users;

    float* out_f    = (float*)d_out;
    float* u_emb    = out_f;                          // tuple order: (u_emb, neighbor)
    float* neighbor = out_f + (size_t)n_users * D_C;

    float *nb_base; int2 *bpk; int *cnt, *off, *cur, *part;
    cudaGetSymbolAddress((void**)&nb_base, g_nb);
    cudaGetSymbolAddress((void**)&bpk,     g_bpk);
    cudaGetSymbolAddress((void**)&cnt,     g_cnt);
    cudaGetSymbolAddress((void**)&off,     g_off);
    cudaGetSymbolAddress((void**)&cur,     g_cur);
    cudaGetSymbolAddress((void**)&part,    g_part);

    float* nb0 = nb_base;
    float* nb1 = nb_base + (size_t)n_items * D_C;
    float* nb2 = nb_base + (size_t)2 * n_items * D_C;

    // --- build CSR bins -----------------------------------------------------
    cudaMemsetAsync(cnt, 0, (size_t)nrows * sizeof(int), 0);
    for (int r = 0; r < 4; r++) {
        int b = (r < 3) ? r * n_items : n3;
        int g = ((nE[r] + 3) / 4 + 255) / 256;
        hist_kernel<<<g, 256>>>(dsts[r], nE[r], b, cnt);
    }
    int nparts = (nrows + SCAN_CHUNK - 1) / SCAN_CHUNK;
    block_sum_kernel<<<nparts, 1024>>>(cnt, part, nrows);
    part_scan_kernel<<<1, 1024>>>(part, nparts, off + nrows);
    scan_final_kernel<<<nparts, 1024>>>(cnt, part, off, cur, nrows);
    for (int r = 0; r < 4; r++) {
        int b = (r < 3) ? r * n_items : n3;
        int g = (nE[r] + 255) / 256;
        scatter_kernel<<<g, 256>>>(srcs[r], dsts[r], vals[r], nE[r], b, cur, bpk);
    }

    // --- gather-accumulate: writes nb0..2 and u_emb (no memset needed) -------
    {
        int g = ((nrows * 32) + 255) / 256;
        gather_kernel<<<g, 256>>>(off, bpk, x, nb_base, u_emb, n3, nrows);
    }

    // --- score + combine ------------------------------------------------------
    const int smem_bytes = (64 * PITCHI + 64 * PITCH + 3 * 64) * (int)sizeof(float);
    cudaFuncSetAttribute(score_kernel,
                         cudaFuncAttributeMaxDynamicSharedMemorySize, smem_bytes);
    int nblocks = (n_items + 63) / 64;
    score_kernel<<<nblocks, 256, smem_bytes>>>(x, nb0, nb1, nb2, I0, I1, I2,
                                               neighbor, n_items);
}

// round 11
// speedup vs baseline: 1.6409x; 1.1056x over previous
#include <cuda_runtime.h>
#include <cuda_fp16.h>
#include <math.h>

// ---------------------------------------------------------------------------
// Problem constants (fixed by dataset; runtime sizes still read from in_sizes)
// ---------------------------------------------------------------------------
#define D_C       128
#define PITCH     132          // z_sh row pitch (floats)
#define PITCHI    264          // paired-I row pitch (floats)
#define MAX_ITEMS 200000
#define MAX_USERS 100000
#define MAX_EII   3200000
#define MAX_EUI   1600000
#define MAX_EDGES (3 * MAX_EII + MAX_EUI)          // 11.2M
#define MAX_ROWS  (3 * MAX_ITEMS + MAX_USERS)      // 700K logical output rows
#define SCAN_CHUNK 4096
#define MAX_PARTS ((MAX_ROWS + SCAN_CHUNK - 1) / SCAN_CHUNK + 1)

// Static device scratch (no allocs allowed).
__device__ float   g_nb  [(size_t)3 * MAX_ITEMS * D_C]; // 3 item->item aggregates
__device__ __half2 g_xh  [(size_t)MAX_ITEMS * D_C / 2]; // fp16 copy of x (51MB)
__device__ int2    g_bpk [MAX_EDGES];                   // binned (src, val-bits)
__device__ int     g_cnt [MAX_ROWS];                    // per-row edge counts
__device__ int     g_off [MAX_ROWS + 1];                // CSR row offsets
__device__ int     g_cur [MAX_ROWS];                    // scatter cursors
__device__ int     g_part[MAX_PARTS];                   // scan block partials

// ---------------------------------------------------------------------------
// Pass 0: convert x to fp16 (halves the gather kernel's L2 byte traffic;
// val stays fp32 and accumulation stays fp32 — expected rel_err ~3e-4).
// ---------------------------------------------------------------------------
__global__ void x2h_kernel(const float4* __restrict__ x4,
                           __half2* __restrict__ xh, int n4)
{
    int i = blockIdx.x * blockDim.x + threadIdx.x;
    if (i < n4) {
        float4 v = x4[i];
        xh[2 * i]     = __floats2half2_rn(v.x, v.y);
        xh[2 * i + 1] = __floats2half2_rn(v.z, v.w);
    }
}

// ---------------------------------------------------------------------------
// Pass 1: histogram of destination rows (4 edges / thread, int4 loads)
// (unchanged across rounds — serves as the DVFS clock canary in ncu)
// ---------------------------------------------------------------------------
__global__ void hist_kernel(const int* __restrict__ dst, int nE, int base,
                            int* __restrict__ cnt)
{
    int i0 = (blockIdx.x * blockDim.x + threadIdx.x) * 4;
    if (i0 + 3 < nE) {
        int4 d = *reinterpret_cast<const int4*>(dst + i0);
        atomicAdd(&cnt[base + d.x], 1);
        atomicAdd(&cnt[base + d.y], 1);
        atomicAdd(&cnt[base + d.z], 1);
        atomicAdd(&cnt[base + d.w], 1);
    } else {
        for (int j = i0; j < nE; j++) atomicAdd(&cnt[base + dst[j]], 1);
    }
}

// ---------------------------------------------------------------------------
// Pass 2a: per-block sums (4096 elements / block)
// ---------------------------------------------------------------------------
__global__ void __launch_bounds__(1024)
block_sum_kernel(const int* __restrict__ cnt, int* __restrict__ part, int N)
{
    __shared__ int ws[32];
    const int tid = threadIdx.x, lane = tid & 31, wid = tid >> 5;
    int idx = blockIdx.x * SCAN_CHUNK + tid * 4;
    int t = 0;
    if (idx + 3 < N) {
        int4 v = *reinterpret_cast<const int4*>(cnt + idx);
        t = v.x + v.y + v.z + v.w;
    } else {
        for (int j = idx; j < min(idx + 4, N); j++) t += cnt[j];
    }
#pragma unroll
    for (int o = 16; o > 0; o >>= 1) t += __shfl_xor_sync(0xffffffffu, t, o);
    if (lane == 0) ws[wid] = t;
    __syncthreads();
    if (wid == 0) {
        int u = ws[lane];
#pragma unroll
        for (int o = 16; o > 0; o >>= 1) u += __shfl_xor_sync(0xffffffffu, u, o);
        if (lane == 0) part[blockIdx.x] = u;
    }
}

// ---------------------------------------------------------------------------
// Pass 2b: exclusive scan of the (<=1024) block partials; writes off[N]
// ---------------------------------------------------------------------------
__global__ void __launch_bounds__(1024)
part_scan_kernel(int* __restrict__ part, int nparts, int* __restrict__ off_total)
{
    __shared__ int wtot[32];
    const int tid = threadIdx.x, lane = tid & 31, wid = tid >> 5;
    int v = (tid < nparts) ? part[tid] : 0;
    int incl = v;
#pragma unroll
    for (int o = 1; o < 32; o <<= 1) {
        int u = __shfl_up_sync(0xffffffffu, incl, o);
        if (lane >= o) incl += u;
    }
    if (lane == 31) wtot[wid] = incl;
    __syncthreads();
    if (wid == 0) {
        int w = wtot[lane];
        int wi = w;
#pragma unroll
        for (int o = 1; o < 32; o <<= 1) {
            int u = __shfl_up_sync(0xffffffffu, wi, o);
            if (lane >= o) wi += u;
        }
        wtot[lane] = wi - w;     // exclusive warp offsets
    }
    __syncthreads();
    int excl = wtot[wid] + incl - v;
    if (tid < nparts) part[tid] = excl;
    if (tid == nparts - 1) *off_total = excl + v;   // off[N] = grand total
}

// ---------------------------------------------------------------------------
// Pass 2c: final scan — local 4096-chunk scan + per-block carry from part[]
// ---------------------------------------------------------------------------
__global__ void __launch_bounds__(1024)
scan_final_kernel(const int* __restrict__ cnt, const int* __restrict__ part,
                  int* __restrict__ off, int* __restrict__ cur, int N)
{
    __shared__ int wtot[32];
    __shared__ int wexcl[32];
    const int tid = threadIdx.x, lane = tid & 31, wid = tid >> 5;
    int idx = blockIdx.x * SCAN_CHUNK + tid * 4;

    int4 v = make_int4(0, 0, 0, 0);
    if (idx + 3 < N)      v = *reinterpret_cast<const int4*>(cnt + idx);
    else if (idx < N) {
        v.x = cnt[idx];
        if (idx + 1 < N) v.y = cnt[idx + 1];
        if (idx + 2 < N) v.z = cnt[idx + 2];
    }
    int t0 = v.x, t1 = t0 + v.y, t2 = t1 + v.z, t3 = t2 + v.w;

    int incl = t3;
#pragma unroll
    for (int o = 1; o < 32; o <<= 1) {
        int u = __shfl_up_sync(0xffffffffu, incl, o);
        if (lane >= o) incl += u;
    }
    int thr_excl = incl - t3;
    if (lane == 31) wtot[wid] = incl;
    __syncthreads();
    if (wid == 0) {
        int w = wtot[lane];
        int wi = w;
#pragma unroll
        for (int o = 1; o < 32; o <<= 1) {
            int u = __shfl_up_sync(0xffffffffu, wi, o);
            if (lane >= o) wi += u;
        }
        wexcl[lane] = wi - w;
    }
    __syncthreads();
    int ex = part[blockIdx.x] + wexcl[wid] + thr_excl;
    if (idx + 3 < N) {
        int4 o4 = make_int4(ex, ex + t0, ex + t1, ex + t2);
        *reinterpret_cast<int4*>(off + idx) = o4;
        *reinterpret_cast<int4*>(cur + idx) = o4;
    } else if (idx < N) {
        off[idx] = ex;           cur[idx] = ex;
        if (idx + 1 < N) { off[idx + 1] = ex + t0; cur[idx + 1] = ex + t0; }
        if (idx + 2 < N) { off[idx + 2] = ex + t1; cur[idx + 2] = ex + t1; }
    }
}

// ---------------------------------------------------------------------------
// Pass 3: scatter edges into destination bins — ONE packed 8B write per edge
// ---------------------------------------------------------------------------
__global__ void scatter_kernel(const int* __restrict__ src,
                               const int* __restrict__ dst,
                               const float* __restrict__ val,
                               int nE, int base, int* __restrict__ cur,
                               int2* __restrict__ bpk)
{
    int i = blockIdx.x * blockDim.x + threadIdx.x;
    if (i < nE) {
        int d   = dst[i];
        int pos = atomicAdd(&cur[base + d], 1);
        bpk[pos] = make_int2(src[i], __float_as_int(val[i]));
    }
}

// ---------------------------------------------------------------------------
// Pass 4: gather-accumulate from the fp16 x copy. One warp per output row;
// each lane owns 4 columns (one 8B load per edge -> 256B/row vs 512B fp32).
// MLP=2; fp32 accumulation; single 512B fp32 store per row.
// ---------------------------------------------------------------------------
__global__ void __launch_bounds__(256)
gather_kernel(const int* __restrict__ off,
              const int2* __restrict__ bpk,
              const __half2* __restrict__ xh,
              float* __restrict__ nb, float* __restrict__ uemb,
              int n3, int nrows)
{
    int w = (blockIdx.x * blockDim.x + threadIdx.x) >> 5;
    if (w >= nrows) return;
    const int lane = threadIdx.x & 31;

    unsigned long long pol;
    asm("createpolicy.fractional.L2::evict_last.b64 %0, 1.0;" : "=l"(pol));

    int beg = __ldg(off + w);
    int end = __ldg(off + w + 1);

    float4 a0 = make_float4(0.f, 0.f, 0.f, 0.f);
    float4 a1 = make_float4(0.f, 0.f, 0.f, 0.f);

#define XLOADH(D, SRC)                                                         \
    {                                                                          \
        const __half2* xp = xh + (size_t)(SRC) * (D_C / 2) + lane * 2;         \
        asm volatile("ld.global.nc.L2::cache_hint.b64 %0, [%1], %2;"           \
                     : "=l"(D) : "l"(xp), "l"(pol));                           \
    }
#define XFMAH(A, D, V)                                                         \
    {                                                                          \
        unsigned int _lo = (unsigned int)(D);                                  \
        unsigned int _hi = (unsigned int)((D) >> 32);                          \
        float2 _f0 = __half22float2(*reinterpret_cast<__half2*>(&_lo));        \
        float2 _f1 = __half22float2(*reinterpret_cast<__half2*>(&_hi));        \
        A.x = fmaf(_f0.x, V, A.x); A.y = fmaf(_f0.y, V, A.y);                  \
        A.z = fmaf(_f1.x, V, A.z); A.w = fmaf(_f1.y, V, A.w);                  \
    }

    for (int p = beg; p < end; p += 32) {
        int n = min(32, end - p);
        int2 pk = make_int2(0, 0);
        if (lane < n) pk = __ldg(bpk + p + lane);

        int e = 0;
        for (; e + 2 <= n; e += 2) {
            int   s0 = __shfl_sync(0xffffffffu, pk.x, e);
            int   s1 = __shfl_sync(0xffffffffu, pk.x, e + 1);
            float v0 = __int_as_float(__shfl_sync(0xffffffffu, pk.y, e));
            float v1 = __int_as_float(__shfl_sync(0xffffffffu, pk.y, e + 1));
            unsigned long long d0, d1;
            XLOADH(d0, s0); XLOADH(d1, s1);
            XFMAH(a0, d0, v0); XFMAH(a1, d1, v1);
        }
        if (e < n) {
            int   se = __shfl_sync(0xffffffffu, pk.x, e);
            float ve = __int_as_float(__shfl_sync(0xffffffffu, pk.y, e));
            unsigned long long d; XLOADH(d, se); XFMAH(a0, d, ve);
        }
    }
#undef XLOADH
#undef XFMAH

    a0.x += a1.x; a0.y += a1.y; a0.z += a1.z; a0.w += a1.w;

    float* o = (w < n3) ? (nb + (size_t)w * D_C)
                        : (uemb + (size_t)(w - n3) * D_C);
    *reinterpret_cast<float4*>(o + lane * 4) = a0;
}

// ---------------------------------------------------------------------------
// Score + combine kernel: 256 threads (8 warps), 64 rows/block, 8 rows/warp.
// Inner loop: 8 z-broadcast LDS.64 + 4 I LDS.64 (16 crossbar cyc) vs
// 32 FFMA2 (16 issue cyc) -> fma-bound. smem 102KB -> 2 blocks/SM.
// ---------------------------------------------------------------------------
__device__ __forceinline__ unsigned long long ld_u64_smem(const float* p)
{
    return *reinterpret_cast<const unsigned long long*>(p);
}

__global__ void __launch_bounds__(256, 2)
score_kernel(const float* __restrict__ x,
             const float* __restrict__ nb0,
             const float* __restrict__ nb1,
             const float* __restrict__ nb2,
             const float* __restrict__ I0,
             const float* __restrict__ I1,
             const float* __restrict__ I2,
             float* __restrict__ out,
             int nrows)
{
    extern __shared__ float sm[];
    float* I_sh = sm;                              // 64 * PITCHI (paired k rows)
    float* z_sh = sm + 64 * PITCHI;                // 64 * PITCH
    float* s_sh = sm + 64 * PITCHI + 64 * PITCH;   // 3 * 64

    const int tid  = threadIdx.x;
    const int lane = tid & 31;
    const int wid  = tid >> 5;                     // 8 warps
    const int r0   = wid << 3;                     // 8 rows per warp
    const int row0 = blockIdx.x * 64;
    const int rows = min(64, nrows - row0);

    const float4* xg = reinterpret_cast<const float4*>(x);

#pragma unroll 1
    for (int rel = 0; rel < 3; rel++) {
        const float* nbp = (rel == 0) ? nb0 : (rel == 1) ? nb1 : nb2;
        const float* Ip  = (rel == 0) ? I0  : (rel == 1) ? I1  : I2;

        const float4* Ig = reinterpret_cast<const float4*>(Ip);
        for (int idx = tid; idx < 64 * 32; idx += 256) {
            int p  = idx >> 5;
            int j4 = idx & 31;
            float4 ae = Ig[(2 * p)     * 32 + j4];
            float4 ao = Ig[(2 * p + 1) * 32 + j4];
            float* wp = &I_sh[p * PITCHI + (j4 << 3)];
            *reinterpret_cast<float4*>(wp)     = make_float4(ae.x, ao.x, ae.y, ao.y);
            *reinterpret_cast<float4*>(wp + 4) = make_float4(ae.z, ao.z, ae.w, ao.w);
        }
        const float4* ng = reinterpret_cast<const float4*>(nbp);
        for (int idx = tid; idx < 64 * 32; idx += 256) {
            int r  = idx >> 5;
            int k4 = idx & 31;
            float4 zv = make_float4(0.f, 0.f, 0.f, 0.f);
            if (r < rows) {
                size_t offr = (size_t)(row0 + r) * 32 + k4;
                float4 av = xg[offr];
                float4 bv = ng[offr];
                zv.x = av.x * bv.x; zv.y = av.y * bv.y;
                zv.z = av.z * bv.z; zv.w = av.w * bv.w;
            }
            *reinterpret_cast<float4*>(&z_sh[r * PITCH + (k4 << 2)]) = zv;
        }
        __syncthreads();

        unsigned long long acc[8][4];
#pragma unroll
        for (int r = 0; r < 8; r++)
#pragma unroll
            for (int c = 0; c < 4; c++) acc[r][c] = 0ull;

        for (int p = 0; p < 64; p++) {
            unsigned long long zp[8];
#pragma unroll
            for (int r = 0; r < 8; r++)        // broadcast LDS.64: {z[2p], z[2p+1]}
                zp[r] = ld_u64_smem(&z_sh[(r0 + r) * PITCH + 2 * p]);
#pragma unroll
            for (int c = 0; c < 4; c++) {
                unsigned long long bp =
                    ld_u64_smem(&I_sh[p * PITCHI + ((lane + 32 * c) << 1)]);
#pragma unroll
                for (int r = 0; r < 8; r++)
                    asm("fma.rn.f32x2 %0, %1, %2, %0;"
                        : "+l"(acc[r][c]) : "l"(zp[r]), "l"(bp));
            }
        }

#pragma unroll
        for (int r = 0; r < 8; r++) {
            float rs = 0.f;
#pragma unroll
            for (int c = 0; c < 4; c++) {
                float lo = __int_as_float((int)(acc[r][c] & 0xffffffffull));
                float hi = __int_as_float((int)(acc[r][c] >> 32));
                float h  = lo + hi;
                rs += (h >= 0.f) ? h : 0.2f * h;
            }
#pragma unroll
            for (int o = 16; o > 0; o >>= 1)
                rs += __shfl_xor_sync(0xffffffffu, rs, o);
            if (lane == 0)
                s_sh[rel * 64 + r0 + r] = rs * 0.08838834764831845f; // 1/sqrt(128)
        }
        __syncthreads();
    }

    const float4* n0g = reinterpret_cast<const float4*>(nb0);
    const float4* n1g = reinterpret_cast<const float4*>(nb1);
    const float4* n2g = reinterpret_cast<const float4*>(nb2);
    float4* og = reinterpret_cast<float4*>(out);

    for (int idx = tid; idx < 64 * 32; idx += 256) {
        int r  = idx >> 5;
        int c4 = idx & 31;
        if (r >= rows) continue;
        float s0 = s_sh[r];
        float s1 = s_sh[64 + r];
        float s2 = s_sh[128 + r];
        float m  = fmaxf(s0, fmaxf(s1, s2));
        float e0 = __expf(s0 - m);
        float e1 = __expf(s1 - m);
        float e2 = __expf(s2 - m);
        float inv = 1.f / (e0 + e1 + e2);
        float w0 = e0 * inv, w1 = e1 * inv, w2 = e2 * inv;

        size_t offr = (size_t)(row0 + r) * 32 + c4;
        float4 av = n0g[offr], bv = n1g[offr], cv = n2g[offr];
        float4 o;
        o.x = w0 * av.x + w1 * bv.x + w2 * cv.x;
        o.y = w0 * av.y + w1 * bv.y + w2 * cv.y;
        o.z = w0 * av.z + w1 * bv.z + w2 * cv.z;
        o.w = w0 * av.w + w1 * bv.w + w2 * cv.w;
        og[offr] = o;
    }
}

// ---------------------------------------------------------------------------
// Launch
// ---------------------------------------------------------------------------
extern "C" void kernel_launch(void* const* d_in, const int* in_sizes, int n_in,
                              void* d_out, int out_size)
{
    int base = (in_sizes[0] == 1) ? 1 : 0;

    const float* x      = (const float*)d_in[base + 0];
    const int*   srcs[4] = { (const int*)d_in[base + 1], (const int*)d_in[base + 4],
                             (const int*)d_in[base + 7], (const int*)d_in[base + 10] };
    const int*   dsts[4] = { (const int*)d_in[base + 2], (const int*)d_in[base + 5],
                             (const int*)d_in[base + 8], (const int*)d_in[base + 11] };
    const float* vals[4] = { (const float*)d_in[base + 3], (const float*)d_in[base + 6],
                             (const float*)d_in[base + 9], (const float*)d_in[base + 12] };
    const float* I0     = (const float*)d_in[base + 13];
    const float* I1     = (const float*)d_in[base + 14];
    const float* I2     = (const float*)d_in[base + 15];

    int n_items = in_sizes[base + 0] / D_C;
    int nE[4]   = { in_sizes[base + 1], in_sizes[base + 4],
                    in_sizes[base + 7], in_sizes[base + 10] };
    int n_users = out_size / D_C - n_items;
    int n3      = 3 * n_items;
    int nrows   = n3 + n_users;

    float* out_f    = (float*)d_out;
    float* u_emb    = out_f;                          // tuple order: (u_emb, neighbor)
    float* neighbor = out_f + (size_t)n_users * D_C;

    float *nb_base; __half2 *xh; int2 *bpk; int *cnt, *off, *cur, *part;
    cudaGetSymbolAddress((void**)&nb_base, g_nb);
    cudaGetSymbolAddress((void**)&xh,      g_xh);
    cudaGetSymbolAddress((void**)&bpk,     g_bpk);
    cudaGetSymbolAddress((void**)&cnt,     g_cnt);
    cudaGetSymbolAddress((void**)&off,     g_off);
    cudaGetSymbolAddress((void**)&cur,     g_cur);
    cudaGetSymbolAddress((void**)&part,    g_part);

    float* nb0 = nb_base;
    float* nb1 = nb_base + (size_t)n_items * D_C;
    float* nb2 = nb_base + (size_t)2 * n_items * D_C;

    // --- fp16 copy of x -------------------------------------------------------
    {
        int n4 = n_items * D_C / 4;
        x2h_kernel<<<(n4 + 255) / 256, 256>>>(
            reinterpret_cast<const float4*>(x), xh, n4);
    }

    // --- build CSR bins -------------------------------------------------------
    cudaMemsetAsync(cnt, 0, (size_t)nrows * sizeof(int), 0);
    for (int r = 0; r < 4; r++) {
        int b = (r < 3) ? r * n_items : n3;
        int g = ((nE[r] + 3) / 4 + 255) / 256;
        hist_kernel<<<g, 256>>>(dsts[r], nE[r], b, cnt);
    }
    int nparts = (nrows + SCAN_CHUNK - 1) / SCAN_CHUNK;
    block_sum_kernel<<<nparts, 1024>>>(cnt, part, nrows);
    part_scan_kernel<<<1, 1024>>>(part, nparts, off + nrows);
    scan_final_kernel<<<nparts, 1024>>>(cnt, part, off, cur, nrows);
    for (int r = 0; r < 4; r++) {
        int b = (r < 3) ? r * n_items : n3;
        int g = (nE[r] + 255) / 256;
        scatter_kernel<<<g, 256>>>(srcs[r], dsts[r], vals[r], nE[r], b, cur, bpk);
    }

    // --- gather-accumulate (fp16 x, fp32 accum; no memset needed) --------------
    {
        int g = ((nrows * 32) + 255) / 256;
        gather_kernel<<<g, 256>>>(off, bpk, xh, nb_base, u_emb, n3, nrows);
    }

    // --- score + combine -------------------------------------------------------
    const int smem_bytes = (64 * PITCHI + 64 * PITCH + 3 * 64) * (int)sizeof(float);
    cudaFuncSetAttribute(score_kernel,
                         cudaFuncAttributeMaxDynamicSharedMemorySize, smem_bytes);
    int nblocks = (n_items + 63) / 64;
    score_kernel<<<nblocks, 256, smem_bytes>>>(x, nb0, nb1, nb2, I0, I1, I2,
                                               neighbor, n_items);
}